// round 6
// baseline (speedup 1.0000x reference)
#include <cuda_runtime.h>
#include <math.h>

typedef unsigned long long u64;

#define NG 8
#define NT 2048
#define NH 2048
#define NE 8
#define CAP 320
#define NTOK (NG * NT)        // 16384
#define TPW 4                 // tokens per warp
#define TPT 32                // tokens per block (8 warps * 4)
#define NBLK (NTOK / TPT)     // 512
#define BPG (NBLK / NG)       // 64 blocks per group
#define THREADS 256
#define NITER 16              // H chunks of 128 floats

// scratch: permuted W, argmax ids, per-group completion counters.
// g_cnt is tested modulo BPG -> never needs resetting across graph replays.
__device__ float         g_Wp[NE * NH];
__device__ unsigned char g_expert_id[NTOK];
__device__ unsigned int  g_cnt[NG];

__device__ __forceinline__ void fma2(u64& acc, u64 a, u64 b) {
    asm("fma.rn.f32x2 %0, %1, %2, %0;" : "+l"(acc) : "l"(a), "l"(b));
}
__device__ __forceinline__ u64 add2(u64 a, u64 b) {
    u64 r; asm("add.rn.f32x2 %0, %1, %2;" : "=l"(r) : "l"(a), "l"(b));
    return r;
}
__device__ __forceinline__ u64 pack2(float lo, float hi) {
    u64 r; asm("mov.b64 %0, {%1, %2};" : "=l"(r) : "f"(lo), "f"(hi));
    return r;
}
__device__ __forceinline__ u64 dup2(float v) { return pack2(v, v); }
__device__ __forceinline__ void unpack2(u64 v, float& lo, float& hi) {
    asm("mov.b64 {%0, %1}, %2;" : "=f"(lo), "=f"(hi) : "l"(v));
}

// ---------------------------------------------------------------------------
// Pre-kernel: permute W[E][H] into the lane/expert-pair layout.
// float index f = ((i*8 + j*2 + pp)*32 + l)*4 + c
//   -> expert e = 4*pp + c,  h = i*128 + l*4 + j
// A lane's ulonglong2 read then yields packed pairs (e0,e1),(e2,e3) resp.
// (e4,e5),(e6,e7) at consecutive-lane 16B addresses (coalesced LDG.128).
// ---------------------------------------------------------------------------
__global__ void permute_w_kernel(const float* __restrict__ W) {
    int f = blockIdx.x * blockDim.x + threadIdx.x;   // 0..16383
    int c  = f & 3;
    int l  = (f >> 2) & 31;
    int slot = f >> 7;          // i*8 + j*2 + pp
    int pp = slot & 1;
    int j  = (slot >> 1) & 3;
    int i  = slot >> 3;
    int e  = 4 * pp + c;
    int h  = i * 128 + l * 4 + j;
    g_Wp[f] = W[e * NH + h];
}

// ---------------------------------------------------------------------------
// Capacity epilogue: per-group inclusive cumsum of assignments; zero the
// over-capacity one-hot entries. Run by the LAST router block of each group.
// ---------------------------------------------------------------------------
__device__ void capacity_epilogue(int g, float* __restrict__ out) {
    const int tid = threadIdx.x;           // 256
    const int lane = tid & 31, wrp = tid >> 5;

    u64 ids = ((const u64*)g_expert_id)[g * (NT / 8) + tid];

    int c[NE], s[NE];
#pragma unroll
    for (int e = 0; e < NE; e++) c[e] = 0;
#pragma unroll
    for (int i = 0; i < 8; i++) {
        int e = (int)((ids >> (8 * i)) & 0xFFULL);
#pragma unroll
        for (int ee = 0; ee < NE; ee++) c[ee] += (e == ee);
    }
#pragma unroll
    for (int e = 0; e < NE; e++) s[e] = c[e];
#pragma unroll
    for (int off = 1; off < 32; off <<= 1) {
#pragma unroll
        for (int e = 0; e < NE; e++) {
            int v = __shfl_up_sync(0xffffffffu, s[e], off);
            if (lane >= off) s[e] += v;
        }
    }

    __shared__ int wt[8][NE];
    if (lane == 31) {
#pragma unroll
        for (int e = 0; e < NE; e++) wt[wrp][e] = s[e];
    }
    __syncthreads();
    if (tid < NE) {            // exclusive scan of 8 warp totals
        int run = 0;
#pragma unroll
        for (int w = 0; w < 8; w++) {
            int v = wt[w][tid];
            wt[w][tid] = run;
            run += v;
        }
    }
    __syncthreads();

    int base[NE];
#pragma unroll
    for (int e = 0; e < NE; e++) base[e] = (s[e] - c[e]) + wt[wrp][e];

    int run2[NE];
#pragma unroll
    for (int e = 0; e < NE; e++) run2[e] = 0;

    const size_t tok0 = (size_t)g * NT + (size_t)tid * 8;
#pragma unroll
    for (int i = 0; i < 8; i++) {
        int e = (int)((ids >> (8 * i)) & 0xFFULL);
#pragma unroll
        for (int ee = 0; ee < NE; ee++) {
            int inc = (e == ee);
            run2[ee] += inc;
            if (inc && (base[ee] + run2[ee] > CAP))
                out[(tok0 + i) * NE + ee] = 0.0f;
        }
    }
}

// ---------------------------------------------------------------------------
// Router kernel. warp = 4 tokens, lanes span H (coalesced LDG.128).
// Expert-pair packed FFMA2 (acc 32 regs). W read from g_Wp via L1-resident
// coalesced LDG.128 -> zero W smem -> 3 CTAs/SM (24 warps) for latency hiding.
// ---------------------------------------------------------------------------
__global__ __launch_bounds__(THREADS, 3)
void router_kernel(const float4* __restrict__ hs4,
                   const float* __restrict__ bias,
                   float* __restrict__ out) {
    __shared__ float sh_logit[TPT * 9];
    __shared__ int   sh_arg[TPT];

    const int tid  = threadIdx.x;
    const int lane = tid & 31, warp = tid >> 5;

    const int tok0 = blockIdx.x * TPT + warp * TPW;
    const float4* xp = hs4 + (size_t)tok0 * (NH / 4) + lane;
    const ulonglong2* wp = ((const ulonglong2*)g_Wp) + lane;

    u64 acc[TPW][4];
#pragma unroll
    for (int t = 0; t < TPW; t++)
#pragma unroll
        for (int p = 0; p < 4; p++) acc[t][p] = 0ULL;

#pragma unroll 2
    for (int i = 0; i < NITER; i++) {
        // front-batched token loads: 4 independent LDG.128 (DRAM stream)
        float4 xv[TPW];
#pragma unroll
        for (int t = 0; t < TPW; t++)
            xv[t] = xp[t * (NH / 4) + i * 32];

#pragma unroll
        for (int j = 0; j < 4; j++) {
            ulonglong2 wa = __ldg(wp + ((i * 8 + j * 2 + 0) << 5));
            ulonglong2 wb = __ldg(wp + ((i * 8 + j * 2 + 1) << 5));
#pragma unroll
            for (int t = 0; t < TPW; t++) {
                float xs = (j == 0) ? xv[t].x : (j == 1) ? xv[t].y
                         : (j == 2) ? xv[t].z : xv[t].w;
                u64 xd = dup2(xs);
                fma2(acc[t][0], xd, wa.x);
                fma2(acc[t][1], xd, wa.y);
                fma2(acc[t][2], xd, wb.x);
                fma2(acc[t][3], xd, wb.y);
            }
        }
    }

    // butterfly-reduce packed (token, expert-pair) accumulators across warp
#pragma unroll
    for (int off = 16; off; off >>= 1) {
#pragma unroll
        for (int t = 0; t < TPW; t++)
#pragma unroll
            for (int p = 0; p < 4; p++)
                acc[t][p] = add2(acc[t][p],
                                 __shfl_xor_sync(0xffffffffu, acc[t][p], off));
    }
    if (lane == 0) {
#pragma unroll
        for (int t = 0; t < TPW; t++)
#pragma unroll
            for (int p = 0; p < 4; p++) {
                float lo, hi;
                unpack2(acc[t][p], lo, hi);
                sh_logit[(warp * TPW + t) * 9 + 2 * p]     = lo + __ldg(bias + 2 * p);
                sh_logit[(warp * TPW + t) * 9 + 2 * p + 1] = hi + __ldg(bias + 2 * p + 1);
            }
    }
    __syncthreads();

    // softmax stats + argmax (first-max semantics matches jnp.argmax)
    if (tid < TPT) {
        const float* l = sh_logit + tid * 9;
        float best = l[0]; int bi = 0;
#pragma unroll
        for (int e = 1; e < NE; e++) {
            float v = l[e];
            if (v > best) { best = v; bi = e; }
        }
        float s = 0.f;
#pragma unroll
        for (int e = 0; e < NE; e++) s += expf(l[e] - best);
        sh_arg[tid] = bi;
        int gt = blockIdx.x * TPT + tid;
        out[(size_t)NTOK * NE + gt] = 1.0f / s;      // max router prob
        g_expert_id[gt] = (unsigned char)bi;
    }
    __syncthreads();

    // one-hot (pre-capacity) + logits: thread = (token t, expert e)
    {
        int t = tid >> 3, e = tid & 7;
        int gt = blockIdx.x * TPT + t;
        out[(size_t)gt * NE + e] = (e == sh_arg[t]) ? 1.0f : 0.0f;
        out[(size_t)NTOK * NE + NTOK + (size_t)gt * NE + e] = sh_logit[t * 9 + e];
    }

    // ---- fused capacity epilogue: last block of each group runs it ----
    __threadfence();
    __syncthreads();
    __shared__ int s_last;
    if (tid == 0) {
        unsigned int v = atomicAdd(&g_cnt[blockIdx.x / BPG], 1u);
        s_last = ((v & (BPG - 1)) == (BPG - 1));
    }
    __syncthreads();
    if (s_last) {
        __threadfence();   // acquire: see all group blocks' writes
        capacity_epilogue(blockIdx.x / BPG, out);
    }
}

// ---------------------------------------------------------------------------
extern "C" void kernel_launch(void* const* d_in, const int* in_sizes, int n_in,
                              void* d_out, int out_size) {
    const float4* hs = (const float4*)d_in[0];  // [8, 2048, 2048] f32
    const float* W   = (const float*)d_in[1];   // [8, 2048] f32
    const float* b   = (const float*)d_in[2];   // [8] f32
    float* out = (float*)d_out;

    permute_w_kernel<<<NE * NH / 256, 256>>>(W);
    router_kernel<<<NBLK, THREADS>>>(hs, b, out);
}

// round 7
// speedup vs baseline: 1.2411x; 1.2411x over previous
#include <cuda_runtime.h>
#include <math.h>

typedef unsigned long long u64;

#define NG 8
#define NT 2048
#define NH 2048
#define NE 8
#define CAP 320
#define NTOK (NG * NT)        // 16384
#define TPW 8                 // tokens per warp
#define TPBK 64               // tokens per block (8 warps * 8)
#define NBLK (NTOK / TPBK)    // 256 (single wave at 2 CTA/SM)
#define BPG (NBLK / NG)       // 32 blocks per group
#define THREADS 256
#define NITER 16              // H chunks of 128 floats

// scratch: argmax ids; per-group completion counters.
// g_cnt is tested modulo BPG -> never needs resetting across graph replays.
__device__ unsigned char g_expert_id[NTOK];
__device__ unsigned int  g_cnt[NG];

__device__ __forceinline__ void fma2(u64& acc, u64 a, u64 b) {
    asm("fma.rn.f32x2 %0, %1, %2, %0;" : "+l"(acc) : "l"(a), "l"(b));
}
__device__ __forceinline__ u64 add2(u64 a, u64 b) {
    u64 r; asm("add.rn.f32x2 %0, %1, %2;" : "=l"(r) : "l"(a), "l"(b));
    return r;
}
__device__ __forceinline__ u64 pack2(float lo, float hi) {
    u64 r; asm("mov.b64 %0, {%1, %2};" : "=l"(r) : "f"(lo), "f"(hi));
    return r;
}
__device__ __forceinline__ u64 dup2(float v) { return pack2(v, v); }
__device__ __forceinline__ void unpack2(u64 v, float& lo, float& hi) {
    asm("mov.b64 {%0, %1}, %2;" : "=f"(lo), "=f"(hi) : "l"(v));
}

// ---------------------------------------------------------------------------
// Capacity epilogue: per-group inclusive cumsum of assignments; zero the
// over-capacity one-hot entries. Run by the LAST router block of each group.
// ---------------------------------------------------------------------------
__device__ void capacity_epilogue(int g, float* __restrict__ out) {
    const int tid = threadIdx.x;           // 256
    const int lane = tid & 31, wrp = tid >> 5;

    u64 ids = ((const u64*)g_expert_id)[g * (NT / 8) + tid];

    int c[NE], s[NE];
#pragma unroll
    for (int e = 0; e < NE; e++) c[e] = 0;
#pragma unroll
    for (int i = 0; i < 8; i++) {
        int e = (int)((ids >> (8 * i)) & 0xFFULL);
#pragma unroll
        for (int ee = 0; ee < NE; ee++) c[ee] += (e == ee);
    }
#pragma unroll
    for (int e = 0; e < NE; e++) s[e] = c[e];
#pragma unroll
    for (int off = 1; off < 32; off <<= 1) {
#pragma unroll
        for (int e = 0; e < NE; e++) {
            int v = __shfl_up_sync(0xffffffffu, s[e], off);
            if (lane >= off) s[e] += v;
        }
    }

    __shared__ int wt[8][NE];
    if (lane == 31) {
#pragma unroll
        for (int e = 0; e < NE; e++) wt[wrp][e] = s[e];
    }
    __syncthreads();
    if (tid < NE) {            // exclusive scan of 8 warp totals
        int run = 0;
#pragma unroll
        for (int w = 0; w < 8; w++) {
            int v = wt[w][tid];
            wt[w][tid] = run;
            run += v;
        }
    }
    __syncthreads();

    int base[NE];
#pragma unroll
    for (int e = 0; e < NE; e++) base[e] = (s[e] - c[e]) + wt[wrp][e];

    int run2[NE];
#pragma unroll
    for (int e = 0; e < NE; e++) run2[e] = 0;

    const size_t tok0 = (size_t)g * NT + (size_t)tid * 8;
#pragma unroll
    for (int i = 0; i < 8; i++) {
        int e = (int)((ids >> (8 * i)) & 0xFFULL);
#pragma unroll
        for (int ee = 0; ee < NE; ee++) {
            int inc = (e == ee);
            run2[ee] += inc;
            if (inc && (base[ee] + run2[ee] > CAP))
                out[(tok0 + i) * NE + ee] = 0.0f;
        }
    }
}

// ---------------------------------------------------------------------------
// Router kernel. warp = 8 tokens, lanes span H (coalesced LDG.128).
// Front-batched 8 independent LDG.128 per iter -> ~4KB in flight per warp.
// W in smem, expert-pair packed, streamed per-j (4 u64 live) -> no reg spill.
// acc[t][p] holds packed (logit[2p], logit[2p+1]) per token.
// ---------------------------------------------------------------------------
__global__ __launch_bounds__(THREADS, 2)
void router_kernel(const float4* __restrict__ hs4,
                   const float* __restrict__ W,
                   const float* __restrict__ bias,
                   float* __restrict__ out) {
    extern __shared__ char smem[];
    u64*   shw      = (u64*)smem;                       // 8192 u64 = 64 KB
    float* sh_logit = (float*)(shw + NE * NH / 2);      // 64*9
    float* sh_bias  = sh_logit + TPBK * 9;              // 8
    int*   sh_arg   = (int*)(sh_bias + 8);              // 64

    const int tid  = threadIdx.x;
    const int lane = tid & 31, warp = tid >> 5;

    // W permuted for expert-pair packing:
    // word[(i*16 + j*4 + p)*32 + l] = (W[2p][h], W[2p+1][h]),
    //   h = i*128 + l*4 + j  -> per-(i,j) the 4 pair-words are at
    // consecutive-lane u64 addresses (conflict-free LDS.64).
    {
        const float2* W2 = (const float2*)W;
        float* shwf = (float*)shw;
        for (int u = tid; u < NE * NH / 2; u += THREADS) {
            int e = u >> 10;
            int h = (u & 1023) * 2;           // even h; covers (h, h+1)
            float2 w = W2[u];
            int i = h >> 7, l = (h >> 2) & 31, j = h & 3;
            int p = e >> 1, pos = e & 1;
            int w0 = ((i * 16 + j * 4 + p) << 5) + l;
            int w1 = ((i * 16 + (j + 1) * 4 + p) << 5) + l;
            shwf[w0 * 2 + pos] = w.x;
            shwf[w1 * 2 + pos] = w.y;
        }
    }
    if (tid < 8) sh_bias[tid] = bias[tid];
    __syncthreads();

    const int tok0 = blockIdx.x * TPBK + warp * TPW;
    const float4* xp = hs4 + (size_t)tok0 * (NH / 4) + lane;

    u64 acc[TPW][4];
#pragma unroll
    for (int t = 0; t < TPW; t++)
#pragma unroll
        for (int p = 0; p < 4; p++) acc[t][p] = 0ULL;

#pragma unroll 1
    for (int i = 0; i < NITER; i++) {
        // front-batched: 8 independent LDG.128 (512B coalesced each)
        float4 xv[TPW];
#pragma unroll
        for (int t = 0; t < TPW; t++)
            xv[t] = xp[t * (NH / 4) + i * 32];

#pragma unroll
        for (int j = 0; j < 4; j++) {
            u64 w0 = shw[((i * 16 + j * 4 + 0) << 5) + lane];
            u64 w1 = shw[((i * 16 + j * 4 + 1) << 5) + lane];
            u64 w2 = shw[((i * 16 + j * 4 + 2) << 5) + lane];
            u64 w3 = shw[((i * 16 + j * 4 + 3) << 5) + lane];
#pragma unroll
            for (int t = 0; t < TPW; t++) {
                float xs = (j == 0) ? xv[t].x : (j == 1) ? xv[t].y
                         : (j == 2) ? xv[t].z : xv[t].w;
                u64 xd = dup2(xs);
                fma2(acc[t][0], xd, w0);
                fma2(acc[t][1], xd, w1);
                fma2(acc[t][2], xd, w2);
                fma2(acc[t][3], xd, w3);
            }
        }
    }

    // butterfly-reduce packed (token, expert-pair) accumulators across warp
#pragma unroll
    for (int off = 16; off; off >>= 1) {
#pragma unroll
        for (int t = 0; t < TPW; t++)
#pragma unroll
            for (int p = 0; p < 4; p++)
                acc[t][p] = add2(acc[t][p],
                                 __shfl_xor_sync(0xffffffffu, acc[t][p], off));
    }
    if (lane == 0) {
#pragma unroll
        for (int t = 0; t < TPW; t++)
#pragma unroll
            for (int p = 0; p < 4; p++) {
                float lo, hi;
                unpack2(acc[t][p], lo, hi);
                sh_logit[(warp * TPW + t) * 9 + 2 * p]     = lo + sh_bias[2 * p];
                sh_logit[(warp * TPW + t) * 9 + 2 * p + 1] = hi + sh_bias[2 * p + 1];
            }
    }
    __syncthreads();

    // softmax stats + argmax (first-max semantics matches jnp.argmax)
    if (tid < TPBK) {
        const float* l = sh_logit + tid * 9;
        float best = l[0]; int bi = 0;
#pragma unroll
        for (int e = 1; e < NE; e++) {
            float v = l[e];
            if (v > best) { best = v; bi = e; }
        }
        float s = 0.f;
#pragma unroll
        for (int e = 0; e < NE; e++) s += expf(l[e] - best);
        sh_arg[tid] = bi;
        int gt = blockIdx.x * TPBK + tid;
        out[(size_t)NTOK * NE + gt] = 1.0f / s;      // max router prob
        g_expert_id[gt] = (unsigned char)bi;
    }
    __syncthreads();

    // one-hot (pre-capacity) + logits: 512 elems, 2 per thread
#pragma unroll
    for (int k = 0; k < 2; k++) {
        int idx = tid + k * THREADS;      // 0..511
        int t = idx >> 3, e = idx & 7;
        int gt = blockIdx.x * TPBK + t;
        out[(size_t)gt * NE + e] = (e == sh_arg[t]) ? 1.0f : 0.0f;
        out[(size_t)NTOK * NE + NTOK + (size_t)gt * NE + e] = sh_logit[t * 9 + e];
    }

    // ---- fused capacity epilogue: last block of each group runs it ----
    __threadfence();
    __syncthreads();
    __shared__ int s_last;
    if (tid == 0) {
        unsigned int v = atomicAdd(&g_cnt[blockIdx.x / BPG], 1u);
        s_last = ((v & (BPG - 1)) == (BPG - 1));
    }
    __syncthreads();
    if (s_last) {
        __threadfence();   // acquire: see all group blocks' writes
        capacity_epilogue(blockIdx.x / BPG, out);
    }
}

// ---------------------------------------------------------------------------
extern "C" void kernel_launch(void* const* d_in, const int* in_sizes, int n_in,
                              void* d_out, int out_size) {
    const float4* hs = (const float4*)d_in[0];  // [8, 2048, 2048] f32
    const float* W   = (const float*)d_in[1];   // [8, 2048] f32
    const float* b   = (const float*)d_in[2];   // [8] f32
    float* out = (float*)d_out;

    const int smem = NE * NH / 2 * 8            // W u64 (pair-packed)
                   + TPBK * 9 * 4               // logits
                   + 8 * 4                      // bias
                   + TPBK * 4;                  // argmax
    cudaFuncSetAttribute(router_kernel,
                         cudaFuncAttributeMaxDynamicSharedMemorySize, smem);

    router_kernel<<<NBLK, THREADS, smem>>>(hs, W, b, out);
}